// round 1
// baseline (speedup 1.0000x reference)
#include <cuda_runtime.h>
#include <cstdint>

// Problem constants
#define TT 512
#define DD 2048
#define FFDIM 768
#define EE 128
#define KSEL 8

// Tiling
#define BM 32
#define BK 16
#define BN_GU 128
#define BN_DN 256

// -------- scratch (device globals; no allocation allowed) --------
__device__ int   g_cnt[EE];
__device__ int   g_list[EE * TT];              // packed token*8+slot, per expert
__device__ float g_wt[TT * KSEL];              // combine weight per (token,slot)
__device__ float g_H[TT * KSEL * FFDIM];       // 12.6 MB intermediate (pre-scaled by weight)
__device__ float g_P[TT * KSEL * DD];          // 33.5 MB partial outputs per (token,slot)

// -------- packed f32x2 helpers (Blackwell; PTX-only path) --------
__device__ __forceinline__ unsigned long long pack2(float lo, float hi) {
    unsigned long long r;
    asm("mov.b64 %0, {%1, %2};" : "=l"(r) : "f"(lo), "f"(hi));
    return r;
}
__device__ __forceinline__ void unpack2(unsigned long long v, float& lo, float& hi) {
    asm("mov.b64 {%0, %1}, %2;" : "=f"(lo), "=f"(hi) : "l"(v));
}
__device__ __forceinline__ void fma2(unsigned long long& d, unsigned long long a, unsigned long long b) {
    asm("fma.rn.f32x2 %0, %1, %2, %0;" : "+l"(d) : "l"(a), "l"(b));
}

// ---------------------------------------------------------------
__global__ void zero_cnt_kernel() {
    if (threadIdx.x < EE) g_cnt[threadIdx.x] = 0;
}

// ---------------------------------------------------------------
// Router: 1 block per token, 128 threads (one per expert).
__global__ __launch_bounds__(128) void router_kernel(
    const float* __restrict__ x, const float* __restrict__ wg) {
    __shared__ float xs[DD];
    __shared__ float logit[EE];
    __shared__ float red[EE];
    __shared__ int   redi[EE];
    __shared__ float tv[KSEL];
    __shared__ int   ti[KSEL];

    const int t = blockIdx.x;
    const int tid = threadIdx.x;

    // stage token row
    const float4* xr = reinterpret_cast<const float4*>(x + (size_t)t * DD);
    float4* xs4 = reinterpret_cast<float4*>(xs);
    for (int i = tid; i < DD / 4; i += 128) xs4[i] = xr[i];
    __syncthreads();

    // logit for expert `tid` (wg is [D,E], coalesced across tid)
    float acc = 0.f;
#pragma unroll 8
    for (int d = 0; d < DD; d++) acc += xs[d] * wg[d * EE + tid];
    logit[tid] = acc;
    __syncthreads();

    // top-8 by repeated argmax (ties -> lower index, matching lax.top_k)
    for (int k = 0; k < KSEL; k++) {
        red[tid] = logit[tid];
        redi[tid] = tid;
        __syncthreads();
        for (int s = 64; s > 0; s >>= 1) {
            if (tid < s) {
                if (red[tid + s] > red[tid]) {
                    red[tid] = red[tid + s];
                    redi[tid] = redi[tid + s];
                }
            }
            __syncthreads();
        }
        if (tid == 0) {
            tv[k] = red[0];
            ti[k] = redi[0];
            logit[redi[0]] = -1e30f;
        }
        __syncthreads();
    }

    // renormalized weights == softmax over the 8 selected logits (global Z cancels)
    if (tid < KSEL) red[tid] = __expf(tv[tid] - tv[0]);
    __syncthreads();
    if (tid == 0) {
        float s = 0.f;
        for (int k = 0; k < KSEL; k++) s += red[k];
        float inv = 1.f / s;
        for (int k = 0; k < KSEL; k++) {
            int e = ti[k];
            g_wt[t * KSEL + k] = red[k] * inv;
            int pos = atomicAdd(&g_cnt[e], 1);
            g_list[e * TT + pos] = t * KSEL + k;
        }
    }
}

// ---------------------------------------------------------------
// Gate+Up grouped GEMM: C_g = X_e @ Wg_e, C_u = X_e @ Wu_e, then
// H = weight * silu(C_g) * C_u  -> g_H[(t*8+slot)][ff]
// grid: (FF/128, T/32, E); block 256.
__global__ __launch_bounds__(256, 2) void gateup_kernel(
    const float* __restrict__ x,
    const float* __restrict__ wgp,
    const float* __restrict__ wup) {
    const int e = blockIdx.z;
    const int Mi = g_cnt[e];
    const int m0 = blockIdx.y * BM;
    if (m0 >= Mi) return;
    const int n0 = blockIdx.x * BN_GU;
    const int tid = threadIdx.x;
    const int ty = tid >> 5, tx = tid & 31;

    __shared__ unsigned long long Xs[BK][BM];   // activation, value duplicated in both lanes
    __shared__ float Gs[BK][BN_GU];
    __shared__ float Us[BK][BN_GU];
    __shared__ int   s_ts[BM];
    __shared__ int   s_tok[BM];
    __shared__ float s_w[BM];

    if (tid < BM) {
        int mi = m0 + tid;
        int ts = g_list[e * TT + ((mi < Mi) ? mi : 0)];
        s_ts[tid] = ts;
        s_tok[tid] = ts >> 3;
        s_w[tid] = (mi < Mi) ? g_wt[ts] : 0.f;
    }
    __syncthreads();

    unsigned long long accg[4][2] = {};
    unsigned long long accu[4][2] = {};

    const int xm = tid >> 3;            // token row 0..31
    const int xk = (tid & 7) * 2;       // k offset 0..14
    const int tok = s_tok[xm];
    const float* xrow = x + (size_t)tok * DD;

    for (int k0 = 0; k0 < DD; k0 += BK) {
        // stage X tile (packed, duplicated lanes)
        float2 xv = *reinterpret_cast<const float2*>(xrow + k0 + xk);
        Xs[xk][xm]     = pack2(xv.x, xv.x);
        Xs[xk + 1][xm] = pack2(xv.y, xv.y);
        // stage weight tiles (coalesced float4 along FF)
#pragma unroll
        for (int i = 0; i < 2; i++) {
            int idx = tid + i * 256;
            int row = idx >> 5, col = idx & 31;
            const size_t goff = ((size_t)e * DD + k0 + row) * FFDIM + n0 + col * 4;
            float4 gv = *reinterpret_cast<const float4*>(wgp + goff);
            float4 uv = *reinterpret_cast<const float4*>(wup + goff);
            *reinterpret_cast<float4*>(&Gs[row][col * 4]) = gv;
            *reinterpret_cast<float4*>(&Us[row][col * 4]) = uv;
        }
        __syncthreads();

#pragma unroll
        for (int kk = 0; kk < BK; kk++) {
            unsigned long long a[4] = {Xs[kk][ty], Xs[kk][ty + 8], Xs[kk][ty + 16], Xs[kk][ty + 24]};
            const unsigned long long* gp = reinterpret_cast<const unsigned long long*>(&Gs[kk][tx * 4]);
            const unsigned long long* up = reinterpret_cast<const unsigned long long*>(&Us[kk][tx * 4]);
            unsigned long long bg0 = gp[0], bg1 = gp[1];
            unsigned long long bu0 = up[0], bu1 = up[1];
#pragma unroll
            for (int i = 0; i < 4; i++) {
                fma2(accg[i][0], a[i], bg0);
                fma2(accg[i][1], a[i], bg1);
                fma2(accu[i][0], a[i], bu0);
                fma2(accu[i][1], a[i], bu1);
            }
        }
        __syncthreads();
    }

    // epilogue: h = w * u * silu(g)
#pragma unroll
    for (int i = 0; i < 4; i++) {
        int m = ty + 8 * i;
        if (m0 + m < Mi) {
            int ts = s_ts[m];
            float w = s_w[m];
            float g0, g1, u0, u1;
            float4 hv;
            unpack2(accg[i][0], g0, g1);
            unpack2(accu[i][0], u0, u1);
            hv.x = w * u0 * g0 / (1.f + __expf(-g0));
            hv.y = w * u1 * g1 / (1.f + __expf(-g1));
            unpack2(accg[i][1], g0, g1);
            unpack2(accu[i][1], u0, u1);
            hv.z = w * u0 * g0 / (1.f + __expf(-g0));
            hv.w = w * u1 * g1 / (1.f + __expf(-g1));
            *reinterpret_cast<float4*>(g_H + (size_t)ts * FFDIM + n0 + tx * 4) = hv;
        }
    }
}

// ---------------------------------------------------------------
// Down grouped GEMM: g_P[(t*8+slot)][d] = H_row @ Wd_e
// grid: (D/256, T/32, E); block 256.
__global__ __launch_bounds__(256, 2) void down_kernel(const float* __restrict__ wdp) {
    const int e = blockIdx.z;
    const int Mi = g_cnt[e];
    const int m0 = blockIdx.y * BM;
    if (m0 >= Mi) return;
    const int n0 = blockIdx.x * BN_DN;
    const int tid = threadIdx.x;
    const int ty = tid >> 5, tx = tid & 31;

    __shared__ unsigned long long As[BK][BM];
    __shared__ float Bs[BK][BN_DN];
    __shared__ int   s_ts[BM];

    if (tid < BM) {
        int mi = m0 + tid;
        s_ts[tid] = g_list[e * TT + ((mi < Mi) ? mi : 0)];
    }
    __syncthreads();

    unsigned long long acc[4][2][2] = {};

    const int am = tid >> 3;
    const int ak = (tid & 7) * 2;
    const float* arow = g_H + (size_t)s_ts[am] * FFDIM;

    for (int k0 = 0; k0 < FFDIM; k0 += BK) {
        float2 av = *reinterpret_cast<const float2*>(arow + k0 + ak);
        As[ak][am]     = pack2(av.x, av.x);
        As[ak + 1][am] = pack2(av.y, av.y);
#pragma unroll
        for (int i = 0; i < 4; i++) {
            int idx = tid + i * 256;       // 1024 float4 total
            int row = idx >> 6, col = idx & 63;
            const size_t boff = ((size_t)e * FFDIM + k0 + row) * DD + n0 + col * 4;
            float4 bv = *reinterpret_cast<const float4*>(wdp + boff);
            *reinterpret_cast<float4*>(&Bs[row][col * 4]) = bv;
        }
        __syncthreads();

#pragma unroll
        for (int kk = 0; kk < BK; kk++) {
            unsigned long long a[4] = {As[kk][ty], As[kk][ty + 8], As[kk][ty + 16], As[kk][ty + 24]};
            const unsigned long long* b0p = reinterpret_cast<const unsigned long long*>(&Bs[kk][tx * 4]);
            const unsigned long long* b1p = reinterpret_cast<const unsigned long long*>(&Bs[kk][tx * 4 + 128]);
            unsigned long long b00 = b0p[0], b01 = b0p[1];
            unsigned long long b10 = b1p[0], b11 = b1p[1];
#pragma unroll
            for (int i = 0; i < 4; i++) {
                fma2(acc[i][0][0], a[i], b00);
                fma2(acc[i][0][1], a[i], b01);
                fma2(acc[i][1][0], a[i], b10);
                fma2(acc[i][1][1], a[i], b11);
            }
        }
        __syncthreads();
    }

#pragma unroll
    for (int i = 0; i < 4; i++) {
        int m = ty + 8 * i;
        if (m0 + m < Mi) {
            int ts = s_ts[m];
            float* op = g_P + (size_t)ts * DD + n0;
#pragma unroll
            for (int p = 0; p < 2; p++) {
                float4 v;
                unpack2(acc[i][p][0], v.x, v.y);
                unpack2(acc[i][p][1], v.z, v.w);
                *reinterpret_cast<float4*>(op + p * 128 + tx * 4) = v;
            }
        }
    }
}

// ---------------------------------------------------------------
// out[t][d] = sum_k g_P[(t*8+k)][d]
__global__ __launch_bounds__(256) void combine_kernel(float* __restrict__ out) {
    int idx = blockIdx.x * blockDim.x + threadIdx.x;   // over T*D/4
    int t = idx / (DD / 4);
    int d4 = idx % (DD / 4);
    const float4* p = reinterpret_cast<const float4*>(g_P);
    float4 s = make_float4(0.f, 0.f, 0.f, 0.f);
#pragma unroll
    for (int k = 0; k < KSEL; k++) {
        float4 v = p[((size_t)(t * KSEL + k)) * (DD / 4) + d4];
        s.x += v.x; s.y += v.y; s.z += v.z; s.w += v.w;
    }
    reinterpret_cast<float4*>(out)[idx] = s;
}

// ---------------------------------------------------------------
extern "C" void kernel_launch(void* const* d_in, const int* in_sizes, int n_in,
                              void* d_out, int out_size) {
    const float* x   = (const float*)d_in[0];   // [T, D]
    const float* wg  = (const float*)d_in[1];   // [D, E]
    const float* wgp = (const float*)d_in[2];   // [E, D, FF]
    const float* wup = (const float*)d_in[3];   // [E, D, FF]
    const float* wdp = (const float*)d_in[4];   // [E, FF, D]
    float* out = (float*)d_out;                 // [T, D]

    zero_cnt_kernel<<<1, 128>>>();
    router_kernel<<<TT, 128>>>(x, wg);

    dim3 g1(FFDIM / BN_GU, TT / BM, EE);        // (6, 16, 128)
    gateup_kernel<<<g1, 256>>>(x, wgp, wup);

    dim3 g2(DD / BN_DN, TT / BM, EE);           // (8, 16, 128)
    down_kernel<<<g2, 256>>>(wdp);

    combine_kernel<<<(TT * DD / 4) / 256, 256>>>(out);
}